// round 1
// baseline (speedup 1.0000x reference)
#include <cuda_runtime.h>

// ---------------- problem constants ----------------
#define N1V   131072
#define N2V   2368
#define E1V   2097152
#define E2V   37888
#define ROIS  148
#define BSZV  16
#define HIDV  64
#define EMBV  (ROIS * HIDV)      // 9472
#define NSEG  (BSZV * ROIS)      // 2368
#define KSLICE 592               // 9472 / 16
#define NKS    16
#define BN_EPSV 1e-5f
#define LRELU  0.01f

// ---------------- scratch (device globals; no runtime alloc) ----------------
__device__ __align__(16) float g_bufX1[(size_t)N1V * 64];
__device__ __align__(16) float g_bufY1[(size_t)N1V * 64];
__device__ float g_deg1[N1V];
__device__ float g_norm1[E1V];

__device__ __align__(16) float g_bufX2[(size_t)N2V * 64];
__device__ __align__(16) float g_bufY2[(size_t)N2V * 64];
__device__ float g_deg2[N2V];
__device__ float g_norm2[E2V];

__device__ __align__(16) float g_pool1[NSEG * 64];
__device__ float g_cnt1[NSEG];
__device__ __align__(16) float g_pool2[NSEG * 64];
__device__ float g_cnt2[NSEG];

__device__ __align__(16) float g_s[BSZV * EMBV];       // emb + emb_roi
__device__ float g_part[NKS * BSZV * 1000];            // split-K partials
__device__ float g_hidden[BSZV * 1000];

// ---------------- helpers ----------------
__device__ __forceinline__ void red_add_v4(float* p, float a, float b, float c, float d) {
    asm volatile("red.global.add.v4.f32 [%0], {%1,%2,%3,%4};"
                 :: "l"(p), "f"(a), "f"(b), "f"(c), "f"(d) : "memory");
}

// ---------------- kernels ----------------
__global__ void init_kernel() {
    int idx = blockIdx.x * 256 + threadIdx.x;
    if (idx < N1V) g_deg1[idx] = 1.0f;                // self-loop weight 1
    if (idx < N2V) g_deg2[idx] = 1.0f;
    if (idx < NSEG * 64) { g_pool1[idx] = 0.0f; g_pool2[idx] = 0.0f; }
    if (idx < NSEG)      { g_cnt1[idx]  = 0.0f; g_cnt2[idx]  = 0.0f; }
}

__global__ void deg_scatter(const int* __restrict__ dst, const float* __restrict__ ew,
                            float* deg, int E) {
    int e = blockIdx.x * 256 + threadIdx.x;
    if (e < E) atomicAdd(&deg[dst[e]], ew[e]);
}

__global__ void rsqrt_ip(float* v, int n) {
    int i = blockIdx.x * 256 + threadIdx.x;
    if (i < n) v[i] = rsqrtf(v[i]);                   // deg -> deg^{-1/2}
}

__global__ void norm_kernel(const int* __restrict__ src, const int* __restrict__ dst,
                            const float* __restrict__ ew, const float* __restrict__ dinv,
                            float* __restrict__ nrm, int E) {
    int e = blockIdx.x * 256 + threadIdx.x;
    if (e < E) nrm[e] = dinv[src[e]] * ew[e] * dinv[dst[e]];
}

// GEMM: out(n,64) = A(n,K) @ W(K,64). One row per thread; W in smem, uniform-broadcast LDS.
template<int K>
__global__ void gemm_k(const float* __restrict__ A, const float* __restrict__ W,
                       float* __restrict__ out, int n) {
    __shared__ float Ws[K * 64];
    for (int i = threadIdx.x; i < K * 64; i += blockDim.x) Ws[i] = W[i];
    __syncthreads();
    int row = blockIdx.x * blockDim.x + threadIdx.x;
    if (row >= n) return;
    float4 acc[16];
#pragma unroll
    for (int c = 0; c < 16; c++) acc[c] = make_float4(0.f, 0.f, 0.f, 0.f);
    const float4* a4 = reinterpret_cast<const float4*>(A + (size_t)row * K);
#pragma unroll 2
    for (int k4 = 0; k4 < K / 4; k4++) {
        float4 a = a4[k4];
        float av[4] = {a.x, a.y, a.z, a.w};
#pragma unroll
        for (int kk = 0; kk < 4; kk++) {
            const float4* wrow = reinterpret_cast<const float4*>(&Ws[(k4 * 4 + kk) * 64]);
            float s = av[kk];
#pragma unroll
            for (int c = 0; c < 16; c++) {
                float4 w = wrow[c];
                acc[c].x += s * w.x; acc[c].y += s * w.y;
                acc[c].z += s * w.z; acc[c].w += s * w.w;
            }
        }
    }
    float4* o4 = reinterpret_cast<float4*>(out + (size_t)row * 64);
#pragma unroll
    for (int c = 0; c < 16; c++) o4[c] = acc[c];
}

// agg[i,:] = h[i,:] * dinv[i]^2  (self-loop term 1/deg)
__global__ void self_init(const float* __restrict__ h, const float* __restrict__ dinv,
                          float* __restrict__ agg, int total) {
    int idx = blockIdx.x * 256 + threadIdx.x;
    if (idx >= total) return;
    float di = dinv[idx >> 6];
    agg[idx] = h[idx] * di * di;
}

// agg[dst] += h[src] * norm ; 16 threads (float4 each) per edge, vector reductions.
__global__ void edge_scatter(const int* __restrict__ src, const int* __restrict__ dst,
                             const float* __restrict__ nrm, const float* __restrict__ h,
                             float* agg, int E) {
    int idx = blockIdx.x * 256 + threadIdx.x;
    if (idx >= E * 16) return;
    int e = idx >> 4, c4 = idx & 15;
    int sN = src[e], dN = dst[e];
    float nv = nrm[e];
    float4 v = __ldg(reinterpret_cast<const float4*>(h) + (size_t)sN * 16 + c4);
    float* p = agg + (size_t)dN * 64 + c4 * 4;
    red_add_v4(p, v.x * nv, v.y * nv, v.z * nv, v.w * nv);
}

__global__ void relu_bias(const float* __restrict__ in, const float* __restrict__ bias,
                          float* __restrict__ out, int total) {
    int idx = blockIdx.x * 256 + threadIdx.x;
    if (idx >= total) return;
    out[idx] = fmaxf(in[idx] + bias[idx & 63], 0.0f);
}

// pooled sums keyed by seg = batch*148 + roi
__global__ void pool_accum(const float* __restrict__ h, const int* __restrict__ roi,
                           const int* __restrict__ batch, float* pool, float* cnt, int n) {
    int idx = blockIdx.x * 256 + threadIdx.x;
    if (idx >= n * 16) return;
    int i = idx >> 4, c4 = idx & 15;
    int seg = batch[i] * ROIS + roi[i];
    float4 v = __ldg(reinterpret_cast<const float4*>(h) + (size_t)i * 16 + c4);
    red_add_v4(pool + (size_t)seg * 64 + c4 * 4, v.x, v.y, v.z, v.w);
    if (c4 == 0) atomicAdd(&cnt[seg], 1.0f);
}

// means; write embedding / embedding_roi / sum straight into d_out; stash s for MLP
__global__ void pool_finalize(float* __restrict__ out) {
    int idx = blockIdx.x * 256 + threadIdx.x;
    if (idx >= NSEG * 64) return;
    int seg = idx >> 6;
    float e1 = g_pool1[idx] / fmaxf(g_cnt1[seg], 1.0f);
    float e2 = g_pool2[idx] / fmaxf(g_cnt2[seg], 1.0f);
    float sv = e1 + e2;
    out[32 + idx] = e1;
    out[32 + BSZV * EMBV + idx] = e2;
    out[32 + 2 * BSZV * EMBV + idx] = sv;
    g_s[idx] = sv;
}

// split-K partial of s(16,9472) @ Wm1(9472,1000). grid = (8 j-blocks, 16 k-slices), 128 thr.
__global__ void mlp1_partial(const float* __restrict__ Wm1) {
    __shared__ float sm[BSZV * KSLICE];                // 37.9 KB
    int ks = blockIdx.y;
    int k0 = ks * KSLICE;
    for (int i = threadIdx.x; i < BSZV * KSLICE; i += blockDim.x) {
        int b = i / KSLICE, kk = i - b * KSLICE;
        sm[i] = g_s[b * EMBV + k0 + kk];
    }
    __syncthreads();
    int j = blockIdx.x * 128 + threadIdx.x;
    if (j >= 1000) return;
    float acc[BSZV];
#pragma unroll
    for (int b = 0; b < BSZV; b++) acc[b] = 0.0f;
    for (int kk = 0; kk < KSLICE; kk += 4) {
        float w0 = Wm1[(size_t)(k0 + kk) * 1000 + j];
        float w1 = Wm1[(size_t)(k0 + kk + 1) * 1000 + j];
        float w2 = Wm1[(size_t)(k0 + kk + 2) * 1000 + j];
        float w3 = Wm1[(size_t)(k0 + kk + 3) * 1000 + j];
#pragma unroll
        for (int b = 0; b < BSZV; b++) {
            float4 sv = *reinterpret_cast<const float4*>(&sm[b * KSLICE + kk]);
            acc[b] += sv.x * w0 + sv.y * w1 + sv.z * w2 + sv.w * w3;
        }
    }
#pragma unroll
    for (int b = 0; b < BSZV; b++) g_part[((size_t)ks * BSZV + b) * 1000 + j] = acc[b];
}

// reduce partials + bias + BN(eval) + LeakyReLU
__global__ void mlp1_reduce(const float* __restrict__ bm1, const float* __restrict__ gamma,
                            const float* __restrict__ beta, const float* __restrict__ mean,
                            const float* __restrict__ var) {
    int idx = blockIdx.x * 256 + threadIdx.x;
    if (idx >= BSZV * 1000) return;
    int b = idx / 1000, j = idx - b * 1000;
    float v = bm1[j];
#pragma unroll
    for (int ks = 0; ks < NKS; ks++) v += g_part[((size_t)ks * BSZV + b) * 1000 + j];
    float sc = gamma[j] * rsqrtf(var[j] + BN_EPSV);
    v = (v - mean[j]) * sc + beta[j];
    g_hidden[idx] = v > 0.0f ? v : LRELU * v;
}

// logits: hidden(16,1000) @ Wm2(1000,2) + bm2 -> out[0:32]. Warp per (b,o).
__global__ void mlp2_kernel(const float* __restrict__ Wm2, const float* __restrict__ bm2,
                            float* __restrict__ out) {
    int w = threadIdx.x >> 5, lane = threadIdx.x & 31;
    int b = w >> 1, o = w & 1;
    float acc = 0.0f;
    for (int k = lane; k < 1000; k += 32) acc += g_hidden[b * 1000 + k] * Wm2[k * 2 + o];
#pragma unroll
    for (int off = 16; off; off >>= 1) acc += __shfl_down_sync(0xffffffffu, acc, off);
    if (lane == 0) out[b * 2 + o] = acc + bm2[o];
}

// ---------------- launcher ----------------
extern "C" void kernel_launch(void* const* d_in, const int* in_sizes, int n_in,
                              void* d_out, int out_size) {
    const float* x1   = (const float*)d_in[0];
    const int*   nlab = (const int*)  d_in[1];
    const int*   ei1  = (const int*)  d_in[2];
    const float* ew1  = (const float*)d_in[3];
    const int*   bat1 = (const int*)  d_in[4];
    const float* x2   = (const float*)d_in[5];
    const int*   rlab = (const int*)  d_in[6];
    const int*   ei2  = (const int*)  d_in[7];
    const float* ew2  = (const float*)d_in[8];
    const int*   bat2 = (const int*)  d_in[9];
    const float* W1a = (const float*)d_in[10]; const float* b1a = (const float*)d_in[11];
    const float* W1b = (const float*)d_in[12]; const float* b1b = (const float*)d_in[13];
    const float* W2a = (const float*)d_in[14]; const float* b2a = (const float*)d_in[15];
    const float* W2b = (const float*)d_in[16]; const float* b2b = (const float*)d_in[17];
    const float* Wm1 = (const float*)d_in[18]; const float* bm1 = (const float*)d_in[19];
    const float* gam = (const float*)d_in[20]; const float* bet = (const float*)d_in[21];
    const float* bmn = (const float*)d_in[22]; const float* bvr = (const float*)d_in[23];
    const float* Wm2 = (const float*)d_in[24]; const float* bm2 = (const float*)d_in[25];

    const int* src1 = ei1;          const int* dst1 = ei1 + E1V;
    const int* src2 = ei2;          const int* dst2 = ei2 + E2V;

    float *bufX1, *bufY1, *deg1, *nrm1, *bufX2, *bufY2, *deg2, *nrm2, *pool1, *cnt1, *pool2, *cnt2;
    cudaGetSymbolAddress((void**)&bufX1, g_bufX1);
    cudaGetSymbolAddress((void**)&bufY1, g_bufY1);
    cudaGetSymbolAddress((void**)&deg1,  g_deg1);
    cudaGetSymbolAddress((void**)&nrm1,  g_norm1);
    cudaGetSymbolAddress((void**)&bufX2, g_bufX2);
    cudaGetSymbolAddress((void**)&bufY2, g_bufY2);
    cudaGetSymbolAddress((void**)&deg2,  g_deg2);
    cudaGetSymbolAddress((void**)&nrm2,  g_norm2);
    cudaGetSymbolAddress((void**)&pool1, g_pool1);
    cudaGetSymbolAddress((void**)&cnt1,  g_cnt1);
    cudaGetSymbolAddress((void**)&pool2, g_pool2);
    cudaGetSymbolAddress((void**)&cnt2,  g_cnt2);

    float* out = (float*)d_out;

    auto cdiv = [](long long a, long long b) { return (int)((a + b - 1) / b); };

    // init + degree + norm
    init_kernel<<<cdiv(NSEG * 64 > N1V ? NSEG * 64 : N1V, 256), 256>>>();
    deg_scatter<<<cdiv(E1V, 256), 256>>>(dst1, ew1, deg1, E1V);
    deg_scatter<<<cdiv(E2V, 256), 256>>>(dst2, ew2, deg2, E2V);
    rsqrt_ip<<<cdiv(N1V, 256), 256>>>(deg1, N1V);
    rsqrt_ip<<<cdiv(N2V, 256), 256>>>(deg2, N2V);
    norm_kernel<<<cdiv(E1V, 256), 256>>>(src1, dst1, ew1, deg1, nrm1, E1V);
    norm_kernel<<<cdiv(E2V, 256), 256>>>(src2, dst2, ew2, deg2, nrm2, E2V);

    // ---- branch 1 (fine-grained graph) ----
    gemm_k<128><<<cdiv(N1V, 256), 256>>>(x1, W1a, bufX1, N1V);
    self_init<<<cdiv((long long)N1V * 64, 256), 256>>>(bufX1, deg1, bufY1, N1V * 64);
    edge_scatter<<<cdiv((long long)E1V * 16, 256), 256>>>(src1, dst1, nrm1, bufX1, bufY1, E1V);
    relu_bias<<<cdiv((long long)N1V * 64, 256), 256>>>(bufY1, b1a, bufX1, N1V * 64);
    gemm_k<64><<<cdiv(N1V, 256), 256>>>(bufX1, W1b, bufY1, N1V);
    self_init<<<cdiv((long long)N1V * 64, 256), 256>>>(bufY1, deg1, bufX1, N1V * 64);
    edge_scatter<<<cdiv((long long)E1V * 16, 256), 256>>>(src1, dst1, nrm1, bufY1, bufX1, E1V);
    relu_bias<<<cdiv((long long)N1V * 64, 256), 256>>>(bufX1, b1b, bufY1, N1V * 64);
    pool_accum<<<cdiv((long long)N1V * 16, 256), 256>>>(bufY1, nlab, bat1, pool1, cnt1, N1V);

    // ---- branch 2 (ROI graph) ----
    gemm_k<128><<<cdiv(N2V, 256), 256>>>(x2, W2a, bufX2, N2V);
    self_init<<<cdiv(N2V * 64, 256), 256>>>(bufX2, deg2, bufY2, N2V * 64);
    edge_scatter<<<cdiv((long long)E2V * 16, 256), 256>>>(src2, dst2, nrm2, bufX2, bufY2, E2V);
    relu_bias<<<cdiv(N2V * 64, 256), 256>>>(bufY2, b2a, bufX2, N2V * 64);
    gemm_k<64><<<cdiv(N2V, 256), 256>>>(bufX2, W2b, bufY2, N2V);
    self_init<<<cdiv(N2V * 64, 256), 256>>>(bufY2, deg2, bufX2, N2V * 64);
    edge_scatter<<<cdiv((long long)E2V * 16, 256), 256>>>(src2, dst2, nrm2, bufY2, bufX2, E2V);
    relu_bias<<<cdiv(N2V * 64, 256), 256>>>(bufX2, b2b, bufY2, N2V * 64);
    pool_accum<<<cdiv(N2V * 16, 256), 256>>>(bufY2, rlab, bat2, pool2, cnt2, N2V);

    // ---- pooling means + embeddings -> d_out ----
    pool_finalize<<<cdiv(NSEG * 64, 256), 256>>>(out);

    // ---- classifier ----
    mlp1_partial<<<dim3(8, NKS), 128>>>(Wm1);
    mlp1_reduce<<<cdiv(BSZV * 1000, 256), 256>>>(bm1, gam, bet, bmn, bvr);
    mlp2_kernel<<<1, 1024>>>(Wm2, bm2, out);
}

// round 2
// speedup vs baseline: 1.4084x; 1.4084x over previous
#include <cuda_runtime.h>

// ---------------- problem constants ----------------
#define N1V   131072
#define N2V   2368
#define E1V   2097152
#define E2V   37888
#define ROIS  148
#define BSZV  16
#define HIDV  64
#define EMBV  (ROIS * HIDV)      // 9472
#define NSEG  (BSZV * ROIS)      // 2368
#define KSLICE 592               // 9472 / 16
#define NKS    16
#define BN_EPSV 1e-5f
#define LRELU  0.01f

struct __align__(8) EP { int s; float w; };

// ---------------- scratch (device globals; no runtime alloc) ----------------
__device__ __align__(16) float g_bufX1[(size_t)N1V * 64];
__device__ __align__(16) float g_bufY1[(size_t)N1V * 64];
__device__ float g_deg1[N1V];
__device__ int   g_cnti1[N1V];
__device__ int   g_rowptr1[N1V + 1];
__device__ int   g_cursor1[N1V];
__device__ int   g_bsum1[512];
__device__ EP    g_pay1[E1V];

__device__ __align__(16) float g_bufX2[(size_t)N2V * 64];
__device__ __align__(16) float g_bufY2[(size_t)N2V * 64];
__device__ float g_deg2[N2V];
__device__ int   g_cnti2[N2V];
__device__ int   g_rowptr2[N2V + 1];
__device__ int   g_cursor2[N2V];
__device__ int   g_bsum2[512];
__device__ EP    g_pay2[E2V];

__device__ __align__(16) float g_pool1[NSEG * 64];
__device__ float g_cntf1[NSEG];
__device__ __align__(16) float g_pool2[NSEG * 64];
__device__ float g_cntf2[NSEG];

__device__ __align__(16) float g_s[BSZV * EMBV];
__device__ float g_part[NKS * BSZV * 1000];
__device__ float g_hidden[BSZV * 1000];

// ---------------- setup kernels ----------------
__global__ void init_kernel() {
    int idx = blockIdx.x * 256 + threadIdx.x;
    if (idx < N1V) { g_deg1[idx] = 1.0f; g_cnti1[idx] = 0; }
    if (idx < N2V) { g_deg2[idx] = 1.0f; g_cnti2[idx] = 0; }
    if (idx < NSEG * 64) { g_pool1[idx] = 0.0f; g_pool2[idx] = 0.0f; }
    if (idx < NSEG)      { g_cntf1[idx] = 0.0f; g_cntf2[idx] = 0.0f; }
}

__global__ void hist_deg(const int* __restrict__ dst, const float* __restrict__ ew,
                         int* cnti, float* deg, int E) {
    int e = blockIdx.x * 256 + threadIdx.x;
    if (e >= E) return;
    int d = dst[e];
    atomicAdd(&cnti[d], 1);
    atomicAdd(&deg[d], ew[e]);
}

__global__ void rsqrt_ip(float* v, int n) {
    int i = blockIdx.x * 256 + threadIdx.x;
    if (i < n) v[i] = rsqrtf(v[i]);   // deg -> deg^{-1/2}
}

// exclusive scan, stage 1: per-block
__global__ void scan_block(const int* __restrict__ cnt, int* __restrict__ excl,
                           int* __restrict__ bsum, int n) {
    __shared__ int sm[256];
    int i = blockIdx.x * 256 + threadIdx.x;
    int v = (i < n) ? cnt[i] : 0;
    sm[threadIdx.x] = v; __syncthreads();
#pragma unroll
    for (int off = 1; off < 256; off <<= 1) {
        int t = (threadIdx.x >= off) ? sm[threadIdx.x - off] : 0;
        __syncthreads();
        sm[threadIdx.x] += t;
        __syncthreads();
    }
    if (i < n) excl[i] = sm[threadIdx.x] - v;
    if (threadIdx.x == 255) bsum[blockIdx.x] = sm[255];
}

// stage 2: scan block sums (nb <= 512), single block
__global__ void scan_bsum(int* bsum, int nb) {
    __shared__ int sm[512];
    int v = (threadIdx.x < nb) ? bsum[threadIdx.x] : 0;
    sm[threadIdx.x] = v; __syncthreads();
#pragma unroll
    for (int off = 1; off < 512; off <<= 1) {
        int t = (threadIdx.x >= off) ? sm[threadIdx.x - off] : 0;
        __syncthreads();
        sm[threadIdx.x] += t;
        __syncthreads();
    }
    if (threadIdx.x < nb) bsum[threadIdx.x] = sm[threadIdx.x] - v;  // exclusive
}

// stage 3: add offsets, finalize rowptr, copy to cursor
__global__ void scan_add(int* rowptr, int* cursor, const int* __restrict__ bsum,
                         int n, int E) {
    int i = blockIdx.x * 256 + threadIdx.x;
    if (i < n) {
        int r = rowptr[i] + bsum[i >> 8];
        rowptr[i] = r;
        cursor[i] = r;
    }
    if (i == 0) rowptr[n] = E;
}

__global__ void csr_scatter(const int* __restrict__ src, const int* __restrict__ dst,
                            const float* __restrict__ ew, const float* __restrict__ dinv,
                            int* cursor, EP* __restrict__ pay, int E) {
    int e = blockIdx.x * 256 + threadIdx.x;
    if (e >= E) return;
    int s = src[e], d = dst[e];
    EP p; p.s = s; p.w = dinv[s] * ew[e] * dinv[d];
    int pos = atomicAdd(&cursor[d], 1);
    pay[pos] = p;
}

// ---------------- GEMM: out(n,64) = A(n,K) @ W(K,64); packed f32x2 FMA, 2 rows/thread ----
template<int K>
__global__ void __launch_bounds__(128) gemm2r(const float* __restrict__ A,
                                              const float* __restrict__ W,
                                              float* __restrict__ out, int n) {
    __shared__ float Ws[K * 64];
    for (int i = threadIdx.x; i < K * 64; i += 128) Ws[i] = W[i];
    __syncthreads();
    int ra = blockIdx.x * 256 + threadIdx.x;
    int rb = ra + 128;
    if (ra >= n) return;
    bool vb = rb < n;
    double accA[32], accB[32];
#pragma unroll
    for (int c = 0; c < 32; c++) { accA[c] = 0.0; accB[c] = 0.0; }  // bits = {0.f,0.f}
    const float4* a4 = reinterpret_cast<const float4*>(A + (size_t)ra * K);
    const float4* b4 = reinterpret_cast<const float4*>(A + (size_t)rb * K);
#pragma unroll 1
    for (int k4 = 0; k4 < K / 4; k4++) {
        float4 av = a4[k4];
        float4 bv = vb ? b4[k4] : make_float4(0.f, 0.f, 0.f, 0.f);
        float aa[4] = {av.x, av.y, av.z, av.w};
        float bb[4] = {bv.x, bv.y, bv.z, bv.w};
#pragma unroll
        for (int kk = 0; kk < 4; kk++) {
            double ap, bp;
            asm("mov.b64 %0, {%1,%1};" : "=d"(ap) : "f"(aa[kk]));
            asm("mov.b64 %0, {%1,%1};" : "=d"(bp) : "f"(bb[kk]));
            const double* wrow = reinterpret_cast<const double*>(&Ws[(k4 * 4 + kk) * 64]);
#pragma unroll
            for (int c = 0; c < 32; c++) {
                double w = wrow[c];
                asm("fma.rn.f32x2 %0, %1, %2, %0;" : "+d"(accA[c]) : "d"(w), "d"(ap));
                asm("fma.rn.f32x2 %0, %1, %2, %0;" : "+d"(accB[c]) : "d"(w), "d"(bp));
            }
        }
    }
    double2* oa = reinterpret_cast<double2*>(out + (size_t)ra * 64);
#pragma unroll
    for (int c = 0; c < 16; c++) oa[c] = make_double2(accA[2 * c], accA[2 * c + 1]);
    if (vb) {
        double2* ob = reinterpret_cast<double2*>(out + (size_t)rb * 64);
#pragma unroll
        for (int c = 0; c < 16; c++) ob[c] = make_double2(accB[2 * c], accB[2 * c + 1]);
    }
}

// ---------------- fused gather: agg = sum_e nrm*h[src] + h*dinv^2 ; relu(agg+bias) ----
// One warp per dst node, float2 per lane. POOL: red-add into pooled sums instead of store.
template<bool POOL>
__global__ void gather(const EP* __restrict__ pay, const int* __restrict__ rowptr,
                       const float* __restrict__ h, const float* __restrict__ dinv,
                       const float* __restrict__ bias, float* __restrict__ out,
                       const int* __restrict__ roi, const int* __restrict__ bat,
                       float* pool, float* cntf, int n) {
    int warp = (blockIdx.x * blockDim.x + threadIdx.x) >> 5;
    int lane = threadIdx.x & 31;
    if (warp >= n) return;
    int beg = rowptr[warp], end = rowptr[warp + 1];
    const float2* h2 = reinterpret_cast<const float2*>(h);
    float di = dinv[warp];
    float sl = di * di;
    float2 hv = h2[(size_t)warp * 32 + lane];
    float ax = hv.x * sl, ay = hv.y * sl;
    for (int e = beg; e < end; e++) {
        EP p = pay[e];                                    // uniform LDG.64 (warp-broadcast)
        float2 v = h2[(size_t)p.s * 32 + lane];
        ax += v.x * p.w;
        ay += v.y * p.w;
    }
    float2 b2 = reinterpret_cast<const float2*>(bias)[lane];
    ax = fmaxf(ax + b2.x, 0.0f);
    ay = fmaxf(ay + b2.y, 0.0f);
    if (POOL) {
        int seg = bat[warp] * ROIS + roi[warp];
        float* p = pool + (size_t)seg * 64 + lane * 2;
        asm volatile("red.global.add.v2.f32 [%0], {%1,%2};"
                     :: "l"(p), "f"(ax), "f"(ay) : "memory");
        if (lane == 0) atomicAdd(&cntf[seg], 1.0f);
    } else {
        reinterpret_cast<float2*>(out)[(size_t)warp * 32 + lane] = make_float2(ax, ay);
    }
}

// ---------------- pooling means + embeddings -> d_out ----------------
__global__ void pool_finalize(float* __restrict__ out) {
    int idx = blockIdx.x * 256 + threadIdx.x;
    if (idx >= NSEG * 64) return;
    int seg = idx >> 6;
    float e1 = g_pool1[idx] / fmaxf(g_cntf1[seg], 1.0f);
    float e2 = g_pool2[idx] / fmaxf(g_cntf2[seg], 1.0f);
    float sv = e1 + e2;
    out[32 + idx] = e1;
    out[32 + BSZV * EMBV + idx] = e2;
    out[32 + 2 * BSZV * EMBV + idx] = sv;
    g_s[idx] = sv;
}

// ---------------- classifier ----------------
__global__ void mlp1_partial(const float* __restrict__ Wm1) {
    __shared__ float sm[BSZV * KSLICE];
    int ks = blockIdx.y;
    int k0 = ks * KSLICE;
    for (int i = threadIdx.x; i < BSZV * KSLICE; i += blockDim.x) {
        int b = i / KSLICE, kk = i - b * KSLICE;
        sm[i] = g_s[b * EMBV + k0 + kk];
    }
    __syncthreads();
    int j = blockIdx.x * 128 + threadIdx.x;
    if (j >= 1000) return;
    float acc[BSZV];
#pragma unroll
    for (int b = 0; b < BSZV; b++) acc[b] = 0.0f;
    for (int kk = 0; kk < KSLICE; kk += 4) {
        float w0 = Wm1[(size_t)(k0 + kk) * 1000 + j];
        float w1 = Wm1[(size_t)(k0 + kk + 1) * 1000 + j];
        float w2 = Wm1[(size_t)(k0 + kk + 2) * 1000 + j];
        float w3 = Wm1[(size_t)(k0 + kk + 3) * 1000 + j];
#pragma unroll
        for (int b = 0; b < BSZV; b++) {
            float4 sv = *reinterpret_cast<const float4*>(&sm[b * KSLICE + kk]);
            acc[b] += sv.x * w0 + sv.y * w1 + sv.z * w2 + sv.w * w3;
        }
    }
#pragma unroll
    for (int b = 0; b < BSZV; b++) g_part[((size_t)ks * BSZV + b) * 1000 + j] = acc[b];
}

__global__ void mlp1_reduce(const float* __restrict__ bm1, const float* __restrict__ gamma,
                            const float* __restrict__ beta, const float* __restrict__ mean,
                            const float* __restrict__ var) {
    int idx = blockIdx.x * 256 + threadIdx.x;
    if (idx >= BSZV * 1000) return;
    int b = idx / 1000, j = idx - b * 1000;
    float v = bm1[j];
#pragma unroll
    for (int ks = 0; ks < NKS; ks++) v += g_part[((size_t)ks * BSZV + b) * 1000 + j];
    float sc = gamma[j] * rsqrtf(var[j] + BN_EPSV);
    v = (v - mean[j]) * sc + beta[j];
    g_hidden[idx] = v > 0.0f ? v : LRELU * v;
}

__global__ void mlp2_kernel(const float* __restrict__ Wm2, const float* __restrict__ bm2,
                            float* __restrict__ out) {
    int w = threadIdx.x >> 5, lane = threadIdx.x & 31;
    int b = w >> 1, o = w & 1;
    float acc = 0.0f;
    for (int k = lane; k < 1000; k += 32) acc += g_hidden[b * 1000 + k] * Wm2[k * 2 + o];
#pragma unroll
    for (int off = 16; off; off >>= 1) acc += __shfl_down_sync(0xffffffffu, acc, off);
    if (lane == 0) out[b * 2 + o] = acc + bm2[o];
}

// ---------------- launcher ----------------
extern "C" void kernel_launch(void* const* d_in, const int* in_sizes, int n_in,
                              void* d_out, int out_size) {
    const float* x1   = (const float*)d_in[0];
    const int*   nlab = (const int*)  d_in[1];
    const int*   ei1  = (const int*)  d_in[2];
    const float* ew1  = (const float*)d_in[3];
    const int*   bat1 = (const int*)  d_in[4];
    const float* x2   = (const float*)d_in[5];
    const int*   rlab = (const int*)  d_in[6];
    const int*   ei2  = (const int*)  d_in[7];
    const float* ew2  = (const float*)d_in[8];
    const int*   bat2 = (const int*)  d_in[9];
    const float* W1a = (const float*)d_in[10]; const float* b1a = (const float*)d_in[11];
    const float* W1b = (const float*)d_in[12]; const float* b1b = (const float*)d_in[13];
    const float* W2a = (const float*)d_in[14]; const float* b2a = (const float*)d_in[15];
    const float* W2b = (const float*)d_in[16]; const float* b2b = (const float*)d_in[17];
    const float* Wm1 = (const float*)d_in[18]; const float* bm1 = (const float*)d_in[19];
    const float* gam = (const float*)d_in[20]; const float* bet = (const float*)d_in[21];
    const float* bmn = (const float*)d_in[22]; const float* bvr = (const float*)d_in[23];
    const float* Wm2 = (const float*)d_in[24]; const float* bm2 = (const float*)d_in[25];

    const int* src1 = ei1;          const int* dst1 = ei1 + E1V;
    const int* src2 = ei2;          const int* dst2 = ei2 + E2V;

    float *bufX1, *bufY1, *deg1, *bufX2, *bufY2, *deg2, *pool1, *cntf1, *pool2, *cntf2;
    int *cnti1, *rowptr1, *cursor1, *bsum1, *cnti2, *rowptr2, *cursor2, *bsum2;
    EP *pay1, *pay2;
    cudaGetSymbolAddress((void**)&bufX1, g_bufX1);
    cudaGetSymbolAddress((void**)&bufY1, g_bufY1);
    cudaGetSymbolAddress((void**)&deg1,  g_deg1);
    cudaGetSymbolAddress((void**)&cnti1, g_cnti1);
    cudaGetSymbolAddress((void**)&rowptr1, g_rowptr1);
    cudaGetSymbolAddress((void**)&cursor1, g_cursor1);
    cudaGetSymbolAddress((void**)&bsum1, g_bsum1);
    cudaGetSymbolAddress((void**)&pay1,  g_pay1);
    cudaGetSymbolAddress((void**)&bufX2, g_bufX2);
    cudaGetSymbolAddress((void**)&bufY2, g_bufY2);
    cudaGetSymbolAddress((void**)&deg2,  g_deg2);
    cudaGetSymbolAddress((void**)&cnti2, g_cnti2);
    cudaGetSymbolAddress((void**)&rowptr2, g_rowptr2);
    cudaGetSymbolAddress((void**)&cursor2, g_cursor2);
    cudaGetSymbolAddress((void**)&bsum2, g_bsum2);
    cudaGetSymbolAddress((void**)&pay2,  g_pay2);
    cudaGetSymbolAddress((void**)&pool1, g_pool1);
    cudaGetSymbolAddress((void**)&cntf1, g_cntf1);
    cudaGetSymbolAddress((void**)&pool2, g_pool2);
    cudaGetSymbolAddress((void**)&cntf2, g_cntf2);

    float* out = (float*)d_out;
    auto cdiv = [](long long a, long long b) { return (int)((a + b - 1) / b); };

    // init + degree + CSR build
    init_kernel<<<cdiv(NSEG * 64, 256), 256>>>();
    hist_deg<<<cdiv(E1V, 256), 256>>>(dst1, ew1, cnti1, deg1, E1V);
    hist_deg<<<cdiv(E2V, 256), 256>>>(dst2, ew2, cnti2, deg2, E2V);
    rsqrt_ip<<<cdiv(N1V, 256), 256>>>(deg1, N1V);
    rsqrt_ip<<<cdiv(N2V, 256), 256>>>(deg2, N2V);
    scan_block<<<cdiv(N1V, 256), 256>>>(cnti1, rowptr1, bsum1, N1V);
    scan_block<<<cdiv(N2V, 256), 256>>>(cnti2, rowptr2, bsum2, N2V);
    scan_bsum<<<1, 512>>>(bsum1, cdiv(N1V, 256));
    scan_bsum<<<1, 512>>>(bsum2, cdiv(N2V, 256));
    scan_add<<<cdiv(N1V, 256), 256>>>(rowptr1, cursor1, bsum1, N1V, E1V);
    scan_add<<<cdiv(N2V, 256), 256>>>(rowptr2, cursor2, bsum2, N2V, E2V);
    csr_scatter<<<cdiv(E1V, 256), 256>>>(src1, dst1, ew1, deg1, cursor1, pay1, E1V);
    csr_scatter<<<cdiv(E2V, 256), 256>>>(src2, dst2, ew2, deg2, cursor2, pay2, E2V);

    // ---- branch 1 (fine-grained graph) ----
    gemm2r<128><<<cdiv(N1V, 256), 128>>>(x1, W1a, bufX1, N1V);
    gather<false><<<cdiv((long long)N1V * 32, 256), 256>>>(
        pay1, rowptr1, bufX1, deg1, b1a, bufY1, nullptr, nullptr, nullptr, nullptr, N1V);
    gemm2r<64><<<cdiv(N1V, 256), 128>>>(bufY1, W1b, bufX1, N1V);
    gather<true><<<cdiv((long long)N1V * 32, 256), 256>>>(
        pay1, rowptr1, bufX1, deg1, b1b, nullptr, nlab, bat1, pool1, cntf1, N1V);

    // ---- branch 2 (ROI graph) ----
    gemm2r<128><<<cdiv(N2V, 256), 128>>>(x2, W2a, bufX2, N2V);
    gather<false><<<cdiv((long long)N2V * 32, 256), 256>>>(
        pay2, rowptr2, bufX2, deg2, b2a, bufY2, nullptr, nullptr, nullptr, nullptr, N2V);
    gemm2r<64><<<cdiv(N2V, 256), 128>>>(bufY2, W2b, bufX2, N2V);
    gather<true><<<cdiv((long long)N2V * 32, 256), 256>>>(
        pay2, rowptr2, bufX2, deg2, b2b, nullptr, rlab, bat2, pool2, cntf2, N2V);

    // ---- pooling means + embeddings -> d_out ----
    pool_finalize<<<cdiv(NSEG * 64, 256), 256>>>(out);

    // ---- classifier ----
    mlp1_partial<<<dim3(8, NKS), 128>>>(Wm1);
    mlp1_reduce<<<cdiv(BSZV * 1000, 256), 256>>>(bm1, gam, bet, bmn, bvr);
    mlp2_kernel<<<1, 1024>>>(Wm2, bm2, out);
}

// round 3
// speedup vs baseline: 1.8056x; 1.2820x over previous
#include <cuda_runtime.h>

// ---------------- problem constants ----------------
#define N1V   131072
#define N2V   2368
#define E1V   2097152
#define E2V   37888
#define ROIS  148
#define BSZV  16
#define HIDV  64
#define EMBV  (ROIS * HIDV)      // 9472
#define NSEG  (BSZV * ROIS)      // 2368
#define NKS   64
#define KSLICE 148               // 9472 / 64
#define BN_EPSV 1e-5f
#define LRELU  0.01f

#define NB1 512                  // N1V / 256
#define NB2 10                   // ceil(N2V / 256)
#define GB1 512                  // gemm blocks graph1 (256 rows each)
#define GB2 10

struct __align__(8) EP { int s; float w; };

// ---------------- scratch (device globals; no runtime alloc) ----------------
__device__ __align__(16) float g_bufX1[(size_t)N1V * 64];
__device__ __align__(16) float g_bufY1[(size_t)N1V * 64];
__device__ float g_deg1[N1V];
__device__ int   g_cnti1[N1V];
__device__ int   g_rowptr1[N1V + 1];
__device__ int   g_cursor1[N1V];
__device__ int   g_bsum1[512];
__device__ EP    g_pay1[E1V];

__device__ __align__(16) float g_bufX2[(size_t)N2V * 64];
__device__ __align__(16) float g_bufY2[(size_t)N2V * 64];
__device__ float g_deg2[N2V];
__device__ int   g_cnti2[N2V];
__device__ int   g_rowptr2[N2V + 1];
__device__ int   g_cursor2[N2V];
__device__ int   g_bsum2[512];
__device__ EP    g_pay2[E2V];

__device__ __align__(16) float g_pool1[NSEG * 64];
__device__ float g_cntf1[NSEG];
__device__ __align__(16) float g_pool2[NSEG * 64];
__device__ float g_cntf2[NSEG];

__device__ __align__(16) float g_s[BSZV * EMBV];
__device__ float g_part[NKS * BSZV * 1000];
__device__ float g_hidden[BSZV * 1000];

// ---------------- setup kernels ----------------
__global__ void init_kernel() {
    int idx = blockIdx.x * 256 + threadIdx.x;
    if (idx < N1V) { g_deg1[idx] = 1.0f; g_cnti1[idx] = 0; }
    if (idx < N2V) { g_deg2[idx] = 1.0f; g_cnti2[idx] = 0; }
    if (idx < NSEG * 64) { g_pool1[idx] = 0.0f; g_pool2[idx] = 0.0f; }
    if (idx < NSEG)      { g_cntf1[idx] = 0.0f; g_cntf2[idx] = 0.0f; }
}

// degree + edge-count histogram, both graphs in one launch
__global__ void hist_all(const int* __restrict__ dst1, const float* __restrict__ ew1,
                         const int* __restrict__ dst2, const float* __restrict__ ew2) {
    int e = blockIdx.x * 256 + threadIdx.x;
    if (e < E1V) {
        int d = dst1[e];
        atomicAdd(&g_cnti1[d], 1);
        atomicAdd(&g_deg1[d], ew1[e]);
    } else if (e < E1V + E2V) {
        int e2 = e - E1V;
        int d = dst2[e2];
        atomicAdd(&g_cnti2[d], 1);
        atomicAdd(&g_deg2[d], ew2[e2]);
    }
}

__global__ void rsqrt_all() {
    int i = blockIdx.x * 256 + threadIdx.x;
    if (i < N1V) g_deg1[i] = rsqrtf(g_deg1[i]);
    else if (i < N1V + N2V) g_deg2[i - N1V] = rsqrtf(g_deg2[i - N1V]);
}

// exclusive scan stage 1, both graphs (blocks [0,512) -> g1, [512,522) -> g2)
__global__ void scan_block_all() {
    __shared__ int sm[256];
    int gb = blockIdx.x;
    const int* cnt; int* excl; int* bsum; int n; int lb;
    if (gb < NB1) { cnt = g_cnti1; excl = g_rowptr1; bsum = g_bsum1; n = N1V; lb = gb; }
    else          { cnt = g_cnti2; excl = g_rowptr2; bsum = g_bsum2; n = N2V; lb = gb - NB1; }
    int i = lb * 256 + threadIdx.x;
    int v = (i < n) ? cnt[i] : 0;
    sm[threadIdx.x] = v; __syncthreads();
#pragma unroll
    for (int off = 1; off < 256; off <<= 1) {
        int t = (threadIdx.x >= off) ? sm[threadIdx.x - off] : 0;
        __syncthreads();
        sm[threadIdx.x] += t;
        __syncthreads();
    }
    if (i < n) excl[i] = sm[threadIdx.x] - v;
    if (threadIdx.x == 255) bsum[lb] = sm[255];
}

// stage 2: block 0 scans bsum1 (512), block 1 scans bsum2 (10)
__global__ void scan_bsum_all() {
    __shared__ int sm[512];
    int* bsum = (blockIdx.x == 0) ? g_bsum1 : g_bsum2;
    int nb    = (blockIdx.x == 0) ? NB1 : NB2;
    int v = (threadIdx.x < nb) ? bsum[threadIdx.x] : 0;
    sm[threadIdx.x] = v; __syncthreads();
#pragma unroll
    for (int off = 1; off < 512; off <<= 1) {
        int t = (threadIdx.x >= off) ? sm[threadIdx.x - off] : 0;
        __syncthreads();
        sm[threadIdx.x] += t;
        __syncthreads();
    }
    if (threadIdx.x < nb) bsum[threadIdx.x] = sm[threadIdx.x] - v;
}

// stage 3: add block offsets, finalize rowptr, copy cursor — both graphs
__global__ void scan_add_all() {
    int gb = blockIdx.x;
    int* rowptr; int* cursor; const int* bsum; int n; int E; int lb;
    if (gb < NB1) { rowptr = g_rowptr1; cursor = g_cursor1; bsum = g_bsum1; n = N1V; E = E1V; lb = gb; }
    else          { rowptr = g_rowptr2; cursor = g_cursor2; bsum = g_bsum2; n = N2V; E = E2V; lb = gb - NB1; }
    int i = lb * 256 + threadIdx.x;
    if (i < n) {
        int r = rowptr[i] + bsum[i >> 8];
        rowptr[i] = r;
        cursor[i] = r;
    }
    if (i == 0) rowptr[n] = E;
}

__global__ void csr_all(const int* __restrict__ src1, const int* __restrict__ dst1,
                        const float* __restrict__ ew1,
                        const int* __restrict__ src2, const int* __restrict__ dst2,
                        const float* __restrict__ ew2) {
    int e = blockIdx.x * 256 + threadIdx.x;
    if (e < E1V) {
        int s = src1[e], d = dst1[e];
        EP p; p.s = s; p.w = g_deg1[s] * ew1[e] * g_deg1[d];
        int pos = atomicAdd(&g_cursor1[d], 1);
        g_pay1[pos] = p;
    } else if (e < E1V + E2V) {
        int e2 = e - E1V;
        int s = src2[e2], d = dst2[e2];
        EP p; p.s = s; p.w = g_deg2[s] * ew2[e2] * g_deg2[d];
        int pos = atomicAdd(&g_cursor2[d], 1);
        g_pay2[pos] = p;
    }
}

// ---------------- GEMM device body: out(n,64) = A(n,K) @ Ws(K,64), 2 rows/thread ----
template<int K>
__device__ __forceinline__ void gemm_body(const float* __restrict__ A,
                                          const float* __restrict__ Wg,
                                          float* __restrict__ out, int n, int lb) {
    __shared__ float Ws[K * 64];
    for (int i = threadIdx.x; i < K * 64; i += 128) Ws[i] = Wg[i];
    __syncthreads();
    int ra = lb * 256 + threadIdx.x;
    int rb = ra + 128;
    if (ra >= n) return;
    bool vb = rb < n;
    double accA[32], accB[32];
#pragma unroll
    for (int c = 0; c < 32; c++) { accA[c] = 0.0; accB[c] = 0.0; }
    const float4* a4 = reinterpret_cast<const float4*>(A + (size_t)ra * K);
    const float4* b4 = reinterpret_cast<const float4*>(A + (size_t)rb * K);
#pragma unroll 1
    for (int k4 = 0; k4 < K / 4; k4++) {
        float4 av = a4[k4];
        float4 bv = vb ? b4[k4] : make_float4(0.f, 0.f, 0.f, 0.f);
        float aa[4] = {av.x, av.y, av.z, av.w};
        float bb[4] = {bv.x, bv.y, bv.z, bv.w};
#pragma unroll
        for (int kk = 0; kk < 4; kk++) {
            double ap, bp;
            asm("mov.b64 %0, {%1,%1};" : "=d"(ap) : "f"(aa[kk]));
            asm("mov.b64 %0, {%1,%1};" : "=d"(bp) : "f"(bb[kk]));
            const double* wrow = reinterpret_cast<const double*>(&Ws[(k4 * 4 + kk) * 64]);
#pragma unroll
            for (int c = 0; c < 32; c++) {
                double w = wrow[c];
                asm("fma.rn.f32x2 %0, %1, %2, %0;" : "+d"(accA[c]) : "d"(w), "d"(ap));
                asm("fma.rn.f32x2 %0, %1, %2, %0;" : "+d"(accB[c]) : "d"(w), "d"(bp));
            }
        }
    }
    double2* oa = reinterpret_cast<double2*>(out + (size_t)ra * 64);
#pragma unroll
    for (int c = 0; c < 16; c++) oa[c] = make_double2(accA[2 * c], accA[2 * c + 1]);
    if (vb) {
        double2* ob = reinterpret_cast<double2*>(out + (size_t)rb * 64);
#pragma unroll
        for (int c = 0; c < 16; c++) ob[c] = make_double2(accB[2 * c], accB[2 * c + 1]);
    }
}

// fused: both graphs, one layer. blocks [0,GB1) graph1, [GB1,GB1+GB2) graph2.
template<int K>
__global__ void __launch_bounds__(128) gemm_all(const float* __restrict__ A1,
                                                const float* __restrict__ W1,
                                                float* __restrict__ o1,
                                                const float* __restrict__ A2,
                                                const float* __restrict__ W2,
                                                float* __restrict__ o2) {
    int gb = blockIdx.x;
    if (gb < GB1) gemm_body<K>(A1, W1, o1, N1V, gb);
    else          gemm_body<K>(A2, W2, o2, N2V, gb - GB1);
}

// ---------------- fused gather (both graphs): relu(sum nrm*h[src] + h/deg + bias) ----
template<bool POOL>
__global__ void gather_all(const float* __restrict__ h1, const float* __restrict__ bias1,
                           float* __restrict__ out1,
                           const float* __restrict__ h2g, const float* __restrict__ bias2,
                           float* __restrict__ out2,
                           const int* __restrict__ roi1, const int* __restrict__ bat1,
                           const int* __restrict__ roi2, const int* __restrict__ bat2) {
    int w = (blockIdx.x * blockDim.x + threadIdx.x) >> 5;
    int lane = threadIdx.x & 31;
    const EP* pay; const int* rowptr; const float* h; const float* dinv; const float* bias;
    float* out; const int* roi; const int* bat; float* pool; float* cntf;
    int node;
    if (w < N1V) {
        node = w; pay = g_pay1; rowptr = g_rowptr1; h = h1; dinv = g_deg1; bias = bias1;
        out = out1; roi = roi1; bat = bat1; pool = g_pool1; cntf = g_cntf1;
    } else if (w < N1V + N2V) {
        node = w - N1V; pay = g_pay2; rowptr = g_rowptr2; h = h2g; dinv = g_deg2; bias = bias2;
        out = out2; roi = roi2; bat = bat2; pool = g_pool2; cntf = g_cntf2;
    } else return;

    int beg = rowptr[node], end = rowptr[node + 1];
    const float2* h2 = reinterpret_cast<const float2*>(h);
    float di = dinv[node];
    float sl = di * di;
    float2 hv = h2[(size_t)node * 32 + lane];
    float ax = hv.x * sl, ay = hv.y * sl;

    int e = beg;
    // 4-deep software pipeline: 4 independent payload loads, then 4 gathers (MLP=4)
    for (; e + 4 <= end; e += 4) {
        EP p0 = pay[e + 0];
        EP p1 = pay[e + 1];
        EP p2 = pay[e + 2];
        EP p3 = pay[e + 3];
        float2 v0 = h2[(size_t)p0.s * 32 + lane];
        float2 v1 = h2[(size_t)p1.s * 32 + lane];
        float2 v2 = h2[(size_t)p2.s * 32 + lane];
        float2 v3 = h2[(size_t)p3.s * 32 + lane];
        ax += v0.x * p0.w; ay += v0.y * p0.w;
        ax += v1.x * p1.w; ay += v1.y * p1.w;
        ax += v2.x * p2.w; ay += v2.y * p2.w;
        ax += v3.x * p3.w; ay += v3.y * p3.w;
    }
    for (; e < end; e++) {
        EP p = pay[e];
        float2 v = h2[(size_t)p.s * 32 + lane];
        ax += v.x * p.w;
        ay += v.y * p.w;
    }
    float2 b2 = reinterpret_cast<const float2*>(bias)[lane];
    ax = fmaxf(ax + b2.x, 0.0f);
    ay = fmaxf(ay + b2.y, 0.0f);
    if (POOL) {
        int seg = bat[node] * ROIS + roi[node];
        float* p = pool + (size_t)seg * 64 + lane * 2;
        asm volatile("red.global.add.v2.f32 [%0], {%1,%2};"
                     :: "l"(p), "f"(ax), "f"(ay) : "memory");
        if (lane == 0) atomicAdd(&cntf[seg], 1.0f);
    } else {
        reinterpret_cast<float2*>(out)[(size_t)node * 32 + lane] = make_float2(ax, ay);
    }
}

// ---------------- pooling means + embeddings -> d_out ----------------
__global__ void pool_finalize(float* __restrict__ out) {
    int idx = blockIdx.x * 256 + threadIdx.x;
    if (idx >= NSEG * 64) return;
    int seg = idx >> 6;
    float e1 = g_pool1[idx] / fmaxf(g_cntf1[seg], 1.0f);
    float e2 = g_pool2[idx] / fmaxf(g_cntf2[seg], 1.0f);
    float sv = e1 + e2;
    out[32 + idx] = e1;
    out[32 + BSZV * EMBV + idx] = e2;
    out[32 + 2 * BSZV * EMBV + idx] = sv;
    g_s[idx] = sv;
}

// ---------------- classifier ----------------
// split-K partials: grid (8 j-blocks, 64 k-slices), 128 thr. KSLICE=148.
__global__ void mlp1_partial(const float* __restrict__ Wm1) {
    __shared__ float sm[BSZV * KSLICE];   // 9.5 KB
    int ks = blockIdx.y;
    int k0 = ks * KSLICE;
    for (int i = threadIdx.x; i < BSZV * KSLICE; i += blockDim.x) {
        int b = i / KSLICE, kk = i - b * KSLICE;
        sm[i] = g_s[b * EMBV + k0 + kk];
    }
    __syncthreads();
    int j = blockIdx.x * 128 + threadIdx.x;
    if (j >= 1000) return;
    float acc[BSZV];
#pragma unroll
    for (int b = 0; b < BSZV; b++) acc[b] = 0.0f;
#pragma unroll 1
    for (int kk = 0; kk < KSLICE; kk += 4) {
        float w0 = Wm1[(size_t)(k0 + kk) * 1000 + j];
        float w1 = Wm1[(size_t)(k0 + kk + 1) * 1000 + j];
        float w2 = Wm1[(size_t)(k0 + kk + 2) * 1000 + j];
        float w3 = Wm1[(size_t)(k0 + kk + 3) * 1000 + j];
#pragma unroll
        for (int b = 0; b < BSZV; b++) {
            float4 sv = *reinterpret_cast<const float4*>(&sm[b * KSLICE + kk]);
            acc[b] += sv.x * w0 + sv.y * w1 + sv.z * w2 + sv.w * w3;
        }
    }
#pragma unroll
    for (int b = 0; b < BSZV; b++) g_part[((size_t)ks * BSZV + b) * 1000 + j] = acc[b];
}

__global__ void mlp1_reduce(const float* __restrict__ bm1, const float* __restrict__ gamma,
                            const float* __restrict__ beta, const float* __restrict__ mean,
                            const float* __restrict__ var) {
    int idx = blockIdx.x * 256 + threadIdx.x;
    if (idx >= BSZV * 1000) return;
    int b = idx / 1000, j = idx - b * 1000;
    float v = bm1[j];
#pragma unroll 8
    for (int ks = 0; ks < NKS; ks++) v += g_part[((size_t)ks * BSZV + b) * 1000 + j];
    float sc = gamma[j] * rsqrtf(var[j] + BN_EPSV);
    v = (v - mean[j]) * sc + beta[j];
    g_hidden[idx] = v > 0.0f ? v : LRELU * v;
}

__global__ void mlp2_kernel(const float* __restrict__ Wm2, const float* __restrict__ bm2,
                            float* __restrict__ out) {
    int w = threadIdx.x >> 5, lane = threadIdx.x & 31;
    int b = w >> 1, o = w & 1;
    float acc = 0.0f;
    for (int k = lane; k < 1000; k += 32) acc += g_hidden[b * 1000 + k] * Wm2[k * 2 + o];
#pragma unroll
    for (int off = 16; off; off >>= 1) acc += __shfl_down_sync(0xffffffffu, acc, off);
    if (lane == 0) out[b * 2 + o] = acc + bm2[o];
}

// ---------------- launcher ----------------
extern "C" void kernel_launch(void* const* d_in, const int* in_sizes, int n_in,
                              void* d_out, int out_size) {
    const float* x1   = (const float*)d_in[0];
    const int*   nlab = (const int*)  d_in[1];
    const int*   ei1  = (const int*)  d_in[2];
    const float* ew1  = (const float*)d_in[3];
    const int*   bat1 = (const int*)  d_in[4];
    const float* x2   = (const float*)d_in[5];
    const int*   rlab = (const int*)  d_in[6];
    const int*   ei2  = (const int*)  d_in[7];
    const float* ew2  = (const float*)d_in[8];
    const int*   bat2 = (const int*)  d_in[9];
    const float* W1a = (const float*)d_in[10]; const float* b1a = (const float*)d_in[11];
    const float* W1b = (const float*)d_in[12]; const float* b1b = (const float*)d_in[13];
    const float* W2a = (const float*)d_in[14]; const float* b2a = (const float*)d_in[15];
    const float* W2b = (const float*)d_in[16]; const float* b2b = (const float*)d_in[17];
    const float* Wm1 = (const float*)d_in[18]; const float* bm1 = (const float*)d_in[19];
    const float* gam = (const float*)d_in[20]; const float* bet = (const float*)d_in[21];
    const float* bmn = (const float*)d_in[22]; const float* bvr = (const float*)d_in[23];
    const float* Wm2 = (const float*)d_in[24]; const float* bm2 = (const float*)d_in[25];

    const int* src1 = ei1;          const int* dst1 = ei1 + E1V;
    const int* src2 = ei2;          const int* dst2 = ei2 + E2V;

    float *bufX1, *bufY1, *bufX2, *bufY2;
    cudaGetSymbolAddress((void**)&bufX1, g_bufX1);
    cudaGetSymbolAddress((void**)&bufY1, g_bufY1);
    cudaGetSymbolAddress((void**)&bufX2, g_bufX2);
    cudaGetSymbolAddress((void**)&bufY2, g_bufY2);

    float* out = (float*)d_out;
    auto cdiv = [](long long a, long long b) { return (int)((a + b - 1) / b); };

    // 1-5: init, histogram, scan (graph-structure build)
    init_kernel<<<cdiv(NSEG * 64, 256), 256>>>();
    hist_all<<<cdiv(E1V + E2V, 256), 256>>>(dst1, ew1, dst2, ew2);
    scan_block_all<<<NB1 + NB2, 256>>>();
    rsqrt_all<<<cdiv(N1V + N2V, 256), 256>>>();
    scan_bsum_all<<<2, 512>>>();
    // 6: layer-A GEMM for both graphs (pure input deps; positioned here so ncu -s 5 profiles it)
    gemm_all<128><<<GB1 + GB2, 128>>>(x1, W1a, bufX1, x2, W2a, bufX2);
    // 7-8: finish CSR
    scan_add_all<<<NB1 + NB2, 256>>>();
    csr_all<<<cdiv(E1V + E2V, 256), 256>>>(src1, dst1, ew1, src2, dst2, ew2);
    // 9: layer-A aggregate + bias + relu (both graphs)
    gather_all<false><<<cdiv((long long)(N1V + N2V) * 32, 256), 256>>>(
        bufX1, b1a, bufY1, bufX2, b2a, bufY2, nullptr, nullptr, nullptr, nullptr);
    // 10: layer-B GEMM (both graphs)
    gemm_all<64><<<GB1 + GB2, 128>>>(bufY1, W1b, bufX1, bufY2, W2b, bufX2);
    // 11: layer-B aggregate + bias + relu + ROI pooling (both graphs)
    gather_all<true><<<cdiv((long long)(N1V + N2V) * 32, 256), 256>>>(
        bufX1, b1b, nullptr, bufX2, b2b, nullptr, nlab, bat1, rlab, bat2);
    // 12: pooled means + embeddings -> d_out
    pool_finalize<<<cdiv(NSEG * 64, 256), 256>>>(out);
    // 13-15: classifier
    mlp1_partial<<<dim3(8, NKS), 128>>>(Wm1);
    mlp1_reduce<<<cdiv(BSZV * 1000, 256), 256>>>(bm1, gam, bet, bmn, bvr);
    mlp2_kernel<<<1, 1024>>>(Wm2, bm2, out);
}

// round 4
// speedup vs baseline: 2.0742x; 1.1488x over previous
#include <cuda_runtime.h>
#include <cuda_fp16.h>

// ---------------- problem constants ----------------
#define N1V   131072
#define N2V   2368
#define E1V   2097152
#define E2V   37888
#define ROIS  148
#define BSZV  16
#define HIDV  64
#define EMBV  (ROIS * HIDV)      // 9472
#define NSEG  (BSZV * ROIS)      // 2368
#define NKS   64
#define KSLICE 148               // 9472 / 64
#define BN_EPSV 1e-5f
#define LRELU  0.01f

#define NB1 512                  // N1V / 256
#define NB2 10                   // ceil(N2V / 256)
#define GB1 512
#define GB2 10

struct __align__(8) EP { int s; float w; };

// ---------------- scratch (device globals; no runtime alloc) ----------------
__device__ __align__(16) __half2 g_bufH1[(size_t)N1V * 32];   // gather input (fp16)
__device__ __align__(16) float   g_bufY1[(size_t)N1V * 64];   // gatherA output (fp32)
__device__ float g_deg1[N1V];
__device__ int   g_cnti1[N1V];
__device__ int   g_rowptr1[N1V + 1];
__device__ int   g_cursor1[N1V];
__device__ int   g_bsum1[512];
__device__ EP    g_pay1[E1V];

__device__ __align__(16) __half2 g_bufH2[(size_t)N2V * 32];
__device__ __align__(16) float   g_bufY2[(size_t)N2V * 64];
__device__ float g_deg2[N2V];
__device__ int   g_cnti2[N2V];
__device__ int   g_rowptr2[N2V + 1];
__device__ int   g_cursor2[N2V];
__device__ int   g_bsum2[512];
__device__ EP    g_pay2[E2V];

__device__ __align__(16) float g_pool1[NSEG * 64];
__device__ float g_cntf1[NSEG];
__device__ __align__(16) float g_pool2[NSEG * 64];
__device__ float g_cntf2[NSEG];

__device__ __align__(16) float g_s[BSZV * EMBV];
__device__ float g_part[NKS * BSZV * 1000];
__device__ float g_hidden[BSZV * 1000];

// ---------------- setup kernels ----------------
__global__ void init_kernel() {
    int idx = blockIdx.x * 256 + threadIdx.x;
    if (idx < N1V) { g_deg1[idx] = 1.0f; g_cnti1[idx] = 0; }
    if (idx < N2V) { g_deg2[idx] = 1.0f; g_cnti2[idx] = 0; }
    if (idx < NSEG * 64) { g_pool1[idx] = 0.0f; g_pool2[idx] = 0.0f; }
    if (idx < NSEG)      { g_cntf1[idx] = 0.0f; g_cntf2[idx] = 0.0f; }
}

__global__ void hist_all(const int* __restrict__ dst1, const float* __restrict__ ew1,
                         const int* __restrict__ dst2, const float* __restrict__ ew2) {
    int e = blockIdx.x * 256 + threadIdx.x;
    if (e < E1V) {
        int d = dst1[e];
        atomicAdd(&g_cnti1[d], 1);
        atomicAdd(&g_deg1[d], ew1[e]);
    } else if (e < E1V + E2V) {
        int e2 = e - E1V;
        int d = dst2[e2];
        atomicAdd(&g_cnti2[d], 1);
        atomicAdd(&g_deg2[d], ew2[e2]);
    }
}

__global__ void rsqrt_all() {
    int i = blockIdx.x * 256 + threadIdx.x;
    if (i < N1V) g_deg1[i] = rsqrtf(g_deg1[i]);
    else if (i < N1V + N2V) g_deg2[i - N1V] = rsqrtf(g_deg2[i - N1V]);
}

__global__ void scan_block_all() {
    __shared__ int sm[256];
    int gb = blockIdx.x;
    const int* cnt; int* excl; int* bsum; int n; int lb;
    if (gb < NB1) { cnt = g_cnti1; excl = g_rowptr1; bsum = g_bsum1; n = N1V; lb = gb; }
    else          { cnt = g_cnti2; excl = g_rowptr2; bsum = g_bsum2; n = N2V; lb = gb - NB1; }
    int i = lb * 256 + threadIdx.x;
    int v = (i < n) ? cnt[i] : 0;
    sm[threadIdx.x] = v; __syncthreads();
#pragma unroll
    for (int off = 1; off < 256; off <<= 1) {
        int t = (threadIdx.x >= off) ? sm[threadIdx.x - off] : 0;
        __syncthreads();
        sm[threadIdx.x] += t;
        __syncthreads();
    }
    if (i < n) excl[i] = sm[threadIdx.x] - v;
    if (threadIdx.x == 255) bsum[lb] = sm[255];
}

__global__ void scan_bsum_all() {
    __shared__ int sm[512];
    int* bsum = (blockIdx.x == 0) ? g_bsum1 : g_bsum2;
    int nb    = (blockIdx.x == 0) ? NB1 : NB2;
    int v = (threadIdx.x < nb) ? bsum[threadIdx.x] : 0;
    sm[threadIdx.x] = v; __syncthreads();
#pragma unroll
    for (int off = 1; off < 512; off <<= 1) {
        int t = (threadIdx.x >= off) ? sm[threadIdx.x - off] : 0;
        __syncthreads();
        sm[threadIdx.x] += t;
        __syncthreads();
    }
    if (threadIdx.x < nb) bsum[threadIdx.x] = sm[threadIdx.x] - v;
}

__global__ void scan_add_all() {
    int gb = blockIdx.x;
    int* rowptr; int* cursor; const int* bsum; int n; int E; int lb;
    if (gb < NB1) { rowptr = g_rowptr1; cursor = g_cursor1; bsum = g_bsum1; n = N1V; E = E1V; lb = gb; }
    else          { rowptr = g_rowptr2; cursor = g_cursor2; bsum = g_bsum2; n = N2V; E = E2V; lb = gb - NB1; }
    int i = lb * 256 + threadIdx.x;
    if (i < n) {
        int r = rowptr[i] + bsum[i >> 8];
        rowptr[i] = r;
        cursor[i] = r;
    }
    if (i == 0) rowptr[n] = E;
}

__global__ void csr_all(const int* __restrict__ src1, const int* __restrict__ dst1,
                        const float* __restrict__ ew1,
                        const int* __restrict__ src2, const int* __restrict__ dst2,
                        const float* __restrict__ ew2) {
    int e = blockIdx.x * 256 + threadIdx.x;
    if (e < E1V) {
        int s = src1[e], d = dst1[e];
        EP p; p.s = s; p.w = g_deg1[s] * ew1[e] * g_deg1[d];
        int pos = atomicAdd(&g_cursor1[d], 1);
        g_pay1[pos] = p;
    } else if (e < E1V + E2V) {
        int e2 = e - E1V;
        int s = src2[e2], d = dst2[e2];
        EP p; p.s = s; p.w = g_deg2[s] * ew2[e2] * g_deg2[d];
        int pos = atomicAdd(&g_cursor2[d], 1);
        g_pay2[pos] = p;
    }
}

// ---------------- GEMM body: outH(n,64 fp16) = A(n,K fp32) @ Ws(K,64), 2 rows/thread ----
template<int K>
__device__ __forceinline__ void gemm_body(const float* __restrict__ A,
                                          const float* __restrict__ Wg,
                                          __half2* __restrict__ outH, int n, int lb) {
    __shared__ float Ws[K * 64];
    for (int i = threadIdx.x; i < K * 64; i += 128) Ws[i] = Wg[i];
    __syncthreads();
    int ra = lb * 256 + threadIdx.x;
    int rb = ra + 128;
    if (ra >= n) return;
    bool vb = rb < n;
    double accA[32], accB[32];
#pragma unroll
    for (int c = 0; c < 32; c++) { accA[c] = 0.0; accB[c] = 0.0; }
    const float4* a4 = reinterpret_cast<const float4*>(A + (size_t)ra * K);
    const float4* b4 = reinterpret_cast<const float4*>(A + (size_t)rb * K);
#pragma unroll 1
    for (int k4 = 0; k4 < K / 4; k4++) {
        float4 av = a4[k4];
        float4 bv = vb ? b4[k4] : make_float4(0.f, 0.f, 0.f, 0.f);
        float aa[4] = {av.x, av.y, av.z, av.w};
        float bb[4] = {bv.x, bv.y, bv.z, bv.w};
#pragma unroll
        for (int kk = 0; kk < 4; kk++) {
            double ap, bp;
            asm("mov.b64 %0, {%1,%1};" : "=d"(ap) : "f"(aa[kk]));
            asm("mov.b64 %0, {%1,%1};" : "=d"(bp) : "f"(bb[kk]));
            const double* wrow = reinterpret_cast<const double*>(&Ws[(k4 * 4 + kk) * 64]);
#pragma unroll
            for (int c = 0; c < 32; c++) {
                double w = wrow[c];
                asm("fma.rn.f32x2 %0, %1, %2, %0;" : "+d"(accA[c]) : "d"(w), "d"(ap));
                asm("fma.rn.f32x2 %0, %1, %2, %0;" : "+d"(accB[c]) : "d"(w), "d"(bp));
            }
        }
    }
    {
        __half2 t[32];
#pragma unroll
        for (int c = 0; c < 32; c++) {
            float lo, hi;
            asm("mov.b64 {%0,%1}, %2;" : "=f"(lo), "=f"(hi) : "d"(accA[c]));
            t[c] = __floats2half2_rn(lo, hi);
        }
        uint4* o = reinterpret_cast<uint4*>(outH + (size_t)ra * 32);
        const uint4* ts = reinterpret_cast<const uint4*>(t);
#pragma unroll
        for (int i = 0; i < 8; i++) o[i] = ts[i];
    }
    if (vb) {
        __half2 t[32];
#pragma unroll
        for (int c = 0; c < 32; c++) {
            float lo, hi;
            asm("mov.b64 {%0,%1}, %2;" : "=f"(lo), "=f"(hi) : "d"(accB[c]));
            t[c] = __floats2half2_rn(lo, hi);
        }
        uint4* o = reinterpret_cast<uint4*>(outH + (size_t)rb * 32);
        const uint4* ts = reinterpret_cast<const uint4*>(t);
#pragma unroll
        for (int i = 0; i < 8; i++) o[i] = ts[i];
    }
}

template<int K>
__global__ void __launch_bounds__(128) gemm_all(const float* __restrict__ A1,
                                                const float* __restrict__ W1,
                                                __half2* __restrict__ o1,
                                                const float* __restrict__ A2,
                                                const float* __restrict__ W2,
                                                __half2* __restrict__ o2) {
    int gb = blockIdx.x;
    if (gb < GB1) gemm_body<K>(A1, W1, o1, N1V, gb);
    else          gemm_body<K>(A2, W2, o2, N2V, gb - GB1);
}

// ---------------- fused gather: relu(sum nrm*h[src] + h/deg + bias); fp16 in, fp32 acc ----
template<bool POOL>
__global__ void gather_all(const __half2* __restrict__ h1, const float* __restrict__ bias1,
                           float* __restrict__ out1,
                           const __half2* __restrict__ h2g, const float* __restrict__ bias2,
                           float* __restrict__ out2,
                           const int* __restrict__ roi1, const int* __restrict__ bat1,
                           const int* __restrict__ roi2, const int* __restrict__ bat2) {
    int w = (blockIdx.x * blockDim.x + threadIdx.x) >> 5;
    int lane = threadIdx.x & 31;
    const EP* pay; const int* rowptr; const __half2* hh; const float* dinv; const float* bias;
    float* out; const int* roi; const int* bat; float* pool; float* cntf;
    int node;
    if (w < N1V) {
        node = w; pay = g_pay1; rowptr = g_rowptr1; hh = h1; dinv = g_deg1; bias = bias1;
        out = out1; roi = roi1; bat = bat1; pool = g_pool1; cntf = g_cntf1;
    } else if (w < N1V + N2V) {
        node = w - N1V; pay = g_pay2; rowptr = g_rowptr2; hh = h2g; dinv = g_deg2; bias = bias2;
        out = out2; roi = roi2; bat = bat2; pool = g_pool2; cntf = g_cntf2;
    } else return;

    int beg = rowptr[node], end = rowptr[node + 1];
    float di = dinv[node];
    float sl = di * di;
    float2 hv = __half22float2(hh[(size_t)node * 32 + lane]);
    float ax = hv.x * sl, ay = hv.y * sl;

    int e = beg;
    // 8-deep software pipeline: batched payload loads, then 8 independent gathers (MLP=8)
    for (; e + 8 <= end; e += 8) {
        EP p[8];
#pragma unroll
        for (int i = 0; i < 8; i++) p[i] = pay[e + i];
        float2 v[8];
#pragma unroll
        for (int i = 0; i < 8; i++) v[i] = __half22float2(hh[(size_t)p[i].s * 32 + lane]);
#pragma unroll
        for (int i = 0; i < 8; i++) { ax += v[i].x * p[i].w; ay += v[i].y * p[i].w; }
    }
    for (; e < end; e++) {
        EP p = pay[e];
        float2 v = __half22float2(hh[(size_t)p.s * 32 + lane]);
        ax += v.x * p.w;
        ay += v.y * p.w;
    }
    float2 b2 = reinterpret_cast<const float2*>(bias)[lane];
    ax = fmaxf(ax + b2.x, 0.0f);
    ay = fmaxf(ay + b2.y, 0.0f);
    if (POOL) {
        int seg = bat[node] * ROIS + roi[node];
        float* p = pool + (size_t)seg * 64 + lane * 2;
        asm volatile("red.global.add.v2.f32 [%0], {%1,%2};"
                     :: "l"(p), "f"(ax), "f"(ay) : "memory");
        if (lane == 0) atomicAdd(&cntf[seg], 1.0f);
    } else {
        reinterpret_cast<float2*>(out)[(size_t)node * 32 + lane] = make_float2(ax, ay);
    }
}

// ---------------- pooling means + embeddings -> d_out ----------------
__global__ void pool_finalize(float* __restrict__ out) {
    int idx = blockIdx.x * 256 + threadIdx.x;
    if (idx >= NSEG * 64) return;
    int seg = idx >> 6;
    float e1 = g_pool1[idx] / fmaxf(g_cntf1[seg], 1.0f);
    float e2 = g_pool2[idx] / fmaxf(g_cntf2[seg], 1.0f);
    float sv = e1 + e2;
    out[32 + idx] = e1;
    out[32 + BSZV * EMBV + idx] = e2;
    out[32 + 2 * BSZV * EMBV + idx] = sv;
    g_s[idx] = sv;
}

// ---------------- classifier ----------------
__global__ void mlp1_partial(const float* __restrict__ Wm1) {
    __shared__ float sm[BSZV * KSLICE];   // 9.5 KB
    int ks = blockIdx.y;
    int k0 = ks * KSLICE;
    for (int i = threadIdx.x; i < BSZV * KSLICE; i += blockDim.x) {
        int b = i / KSLICE, kk = i - b * KSLICE;
        sm[i] = g_s[b * EMBV + k0 + kk];
    }
    __syncthreads();
    int j = blockIdx.x * 128 + threadIdx.x;
    if (j >= 1000) return;
    float acc[BSZV];
#pragma unroll
    for (int b = 0; b < BSZV; b++) acc[b] = 0.0f;
#pragma unroll 1
    for (int kk = 0; kk < KSLICE; kk += 4) {
        float w0 = Wm1[(size_t)(k0 + kk) * 1000 + j];
        float w1 = Wm1[(size_t)(k0 + kk + 1) * 1000 + j];
        float w2 = Wm1[(size_t)(k0 + kk + 2) * 1000 + j];
        float w3 = Wm1[(size_t)(k0 + kk + 3) * 1000 + j];
#pragma unroll
        for (int b = 0; b < BSZV; b++) {
            float4 sv = *reinterpret_cast<const float4*>(&sm[b * KSLICE + kk]);
            acc[b] += sv.x * w0 + sv.y * w1 + sv.z * w2 + sv.w * w3;
        }
    }
#pragma unroll
    for (int b = 0; b < BSZV; b++) g_part[((size_t)ks * BSZV + b) * 1000 + j] = acc[b];
}

__global__ void mlp1_reduce(const float* __restrict__ bm1, const float* __restrict__ gamma,
                            const float* __restrict__ beta, const float* __restrict__ mean,
                            const float* __restrict__ var) {
    int idx = blockIdx.x * 256 + threadIdx.x;
    if (idx >= BSZV * 1000) return;
    int b = idx / 1000, j = idx - b * 1000;
    float v = bm1[j];
#pragma unroll 8
    for (int ks = 0; ks < NKS; ks++) v += g_part[((size_t)ks * BSZV + b) * 1000 + j];
    float sc = gamma[j] * rsqrtf(var[j] + BN_EPSV);
    v = (v - mean[j]) * sc + beta[j];
    g_hidden[idx] = v > 0.0f ? v : LRELU * v;
}

__global__ void mlp2_kernel(const float* __restrict__ Wm2, const float* __restrict__ bm2,
                            float* __restrict__ out) {
    int w = threadIdx.x >> 5, lane = threadIdx.x & 31;
    int b = w >> 1, o = w & 1;
    float acc = 0.0f;
    for (int k = lane; k < 1000; k += 32) acc += g_hidden[b * 1000 + k] * Wm2[k * 2 + o];
#pragma unroll
    for (int off = 16; off; off >>= 1) acc += __shfl_down_sync(0xffffffffu, acc, off);
    if (lane == 0) out[b * 2 + o] = acc + bm2[o];
}

// ---------------- launcher ----------------
extern "C" void kernel_launch(void* const* d_in, const int* in_sizes, int n_in,
                              void* d_out, int out_size) {
    const float* x1   = (const float*)d_in[0];
    const int*   nlab = (const int*)  d_in[1];
    const int*   ei1  = (const int*)  d_in[2];
    const float* ew1  = (const float*)d_in[3];
    const int*   bat1 = (const int*)  d_in[4];
    const float* x2   = (const float*)d_in[5];
    const int*   rlab = (const int*)  d_in[6];
    const int*   ei2  = (const int*)  d_in[7];
    const float* ew2  = (const float*)d_in[8];
    const int*   bat2 = (const int*)  d_in[9];
    const float* W1a = (const float*)d_in[10]; const float* b1a = (const float*)d_in[11];
    const float* W1b = (const float*)d_in[12]; const float* b1b = (const float*)d_in[13];
    const float* W2a = (const float*)d_in[14]; const float* b2a = (const float*)d_in[15];
    const float* W2b = (const float*)d_in[16]; const float* b2b = (const float*)d_in[17];
    const float* Wm1 = (const float*)d_in[18]; const float* bm1 = (const float*)d_in[19];
    const float* gam = (const float*)d_in[20]; const float* bet = (const float*)d_in[21];
    const float* bmn = (const float*)d_in[22]; const float* bvr = (const float*)d_in[23];
    const float* Wm2 = (const float*)d_in[24]; const float* bm2 = (const float*)d_in[25];

    const int* src1 = ei1;          const int* dst1 = ei1 + E1V;
    const int* src2 = ei2;          const int* dst2 = ei2 + E2V;

    __half2 *bufH1, *bufH2;
    float *bufY1, *bufY2;
    cudaGetSymbolAddress((void**)&bufH1, g_bufH1);
    cudaGetSymbolAddress((void**)&bufY1, g_bufY1);
    cudaGetSymbolAddress((void**)&bufH2, g_bufH2);
    cudaGetSymbolAddress((void**)&bufY2, g_bufY2);

    float* out = (float*)d_out;
    auto cdiv = [](long long a, long long b) { return (int)((a + b - 1) / b); };

    // structure build + layer-A GEMM (gemm placed 4th so ncu samples it)
    init_kernel<<<cdiv(NSEG * 64, 256), 256>>>();
    hist_all<<<cdiv(E1V + E2V, 256), 256>>>(dst1, ew1, dst2, ew2);
    rsqrt_all<<<cdiv(N1V + N2V, 256), 256>>>();
    gemm_all<128><<<GB1 + GB2, 128>>>(x1, W1a, bufH1, x2, W2a, bufH2);
    scan_block_all<<<NB1 + NB2, 256>>>();
    scan_bsum_all<<<2, 512>>>();
    scan_add_all<<<NB1 + NB2, 256>>>();
    csr_all<<<cdiv(E1V + E2V, 256), 256>>>(src1, dst1, ew1, src2, dst2, ew2);
    // layer-A aggregate + bias + relu (fp32 out for gemmB)
    gather_all<false><<<cdiv((long long)(N1V + N2V) * 32, 256), 256>>>(
        bufH1, b1a, bufY1, bufH2, b2a, bufY2, nullptr, nullptr, nullptr, nullptr);
    // layer-B GEMM (fp32 in, fp16 out)
    gemm_all<64><<<GB1 + GB2, 128>>>(bufY1, W1b, bufH1, bufY2, W2b, bufH2);
    // layer-B aggregate + bias + relu + ROI pooling
    gather_all<true><<<cdiv((long long)(N1V + N2V) * 32, 256), 256>>>(
        bufH1, b1b, nullptr, bufH2, b2b, nullptr, nlab, bat1, rlab, bat2);
    // pooled means + embeddings -> d_out
    pool_finalize<<<cdiv(NSEG * 64, 256), 256>>>(out);
    // classifier
    mlp1_partial<<<dim3(8, NKS), 128>>>(Wm1);
    mlp1_reduce<<<cdiv(BSZV * 1000, 256), 256>>>(bm1, gam, bet, bmn, bvr);
    mlp2_kernel<<<1, 1024>>>(Wm2, bm2, out);
}